// round 3
// baseline (speedup 1.0000x reference)
#include <cuda_runtime.h>

#define NN 8192
#define DD 128
#define PP 256
#define KK 256
#define DEG 32
#define FF 16
#define TEMP 0.07f
#define FULL 0xffffffffu

// Scratch (__device__ globals; no allocations allowed)
__device__ float g_pos[PP], g_align[PP], g_core[PP], g_neg[KK];
__device__ int   g_count = 0;

__device__ __forceinline__ float warp_sum(float v) {
#pragma unroll
    for (int o = 16; o; o >>= 1) v += __shfl_xor_sync(FULL, v, o);
    return v;
}

__device__ __forceinline__ float dot4(float4 a, float4 b) {
    return a.x * b.x + a.y * b.y + a.z * b.z + a.w * b.w;
}

// ---------------------------------------------------------------------------
// One fused kernel, grid = PP = 256 blocks x 256 threads.
// Block b: neighbor i = nbr_idxs[b] (term1, term2, mu_xy, losses)
//          + negative k = b (warp 7).
// Warp w covers term1 rows j=4w..4w+3 and term2 rows j=4w..4w+3.
// No block syncs until the softmax phase. Last block reduces.
// ---------------------------------------------------------------------------
__global__ void __launch_bounds__(256)
fused_kernel(const float* __restrict__ z,
             const float* __restrict__ et,
             const float* __restrict__ ct,
             const float* __restrict__ core,
             const float* __restrict__ omega,
             const float* __restrict__ phi,
             const int* __restrict__ qidx,
             const int* __restrict__ neg_idxs,
             const int* __restrict__ nbr_idxs,
             const int* __restrict__ neighbors,
             float* __restrict__ out) {
    __shared__ float s_mu1[DEG], s_mu2[DEG], s_te[2 * DEG];
    __shared__ float s_muxy, s_t12[2];
    __shared__ float s_ws[8];
    __shared__ bool  s_isLast;

    const int t = threadIdx.x, lane = t & 31, warp = t >> 5;
    const int b = blockIdx.x;

    // ---- level-0 scalars (independent, broadcast loads) ----
    const int   q    = qidx[0];
    const int   nbr  = nbr_idxs[b];
    const int   negy = neg_idxs[b];
    const float ct0  = ct[0];

    // ---- level-1 gathers: z rows + neighbor indices ----
    const float4 zq4 = ((const float4*)(z + (long long)q * DD))[lane];
    const float4 zi4 = ((const float4*)(z + (long long)nbr * DD))[lane];
    float4 zn4 = make_float4(0.f, 0.f, 0.f, 0.f);
    if (warp == 7) zn4 = ((const float4*)(z + (long long)negy * DD))[lane];

    int myidx = 0;
    if (lane < 8)
        myidx = neighbors[(lane < 4 ? q : nbr) * DEG + 4 * warp + (lane & 3)];

    // ---- level-2 gathers: 8 z rows per warp (idx broadcast via shfl) ----
    float4 row[8];
#pragma unroll
    for (int r = 0; r < 8; r++) {
        const int ri = __shfl_sync(FULL, myidx, r);
        row[r] = ((const float4*)(z + (long long)ri * DD))[lane];
    }
    // level-2: edge-time gathers (lanes 0..7)
    float mydt = 0.f;
    if (lane < 8)
        mydt = ct0 - et[(long long)(lane < 4 ? q : nbr) * NN + myidx];

    // ---- norms of raw z_q / z_i (each warp computes its own) ----
    const float nq_ = warp_sum(dot4(zq4, zq4));
    const float ni_ = warp_sum(dot4(zi4, zi4));
    const float rq  = rsqrtf(fmaxf(nq_, 1e-24f));
    const float riv = rsqrtf(fmaxf(ni_, 1e-24f));
    const float aq  = nq_ * rq * rq;    // ||zq_hat||^2
    const float ai  = ni_ * riv * riv;  // ||zi_hat||^2

    // ---- time encodings: 4 lanes per dt (8 dts per warp) ----
    {
        const float dtv = __shfl_sync(FULL, mydt, lane >> 2);
        const int sub = lane & 3;
        float p = 0.f;
#pragma unroll
        for (int k = 0; k < 4; k++) {
            const int f = 1 + sub + 4 * k;
            if (f < FF) p += __sinf(omega[f] * dtv + phi[f]);
        }
        p += __shfl_xor_sync(FULL, p, 1);
        p += __shfl_xor_sync(FULL, p, 2);
        if (sub == 0) {
            const int g = lane >> 2;
            const float te = omega[0] * dtv + phi[0] + p;
            const int j = 4 * warp + (g & 3);
            if (g < 4) s_te[j] = te;
            else       s_te[DEG + j] = te;
        }
    }

    // ---- row dots: term1 (rows 0..3 vs z_i), term2 (rows 4..7 vs z_q) ----
#pragma unroll
    for (int r = 0; r < 8; r++) {
        const float nr = warp_sum(dot4(row[r], row[r]));
        const float dr = warp_sum(dot4(r < 4 ? zi4 : zq4, row[r]));
        if (lane == 0) {
            const float rr = rsqrtf(fmaxf(nr, 1e-24f));
            const float ar = nr * rr * rr;
            const int j = 4 * warp + (r & 3);
            if (r < 4) s_mu1[j] = -(ai + ar - 2.f * riv * rr * dr);
            else       s_mu2[j] = -(aq + ar - 2.f * rq * rr * dr);
        }
    }

    // ---- mu_xy (warp 0), negative (warp 7), core (thread 0) ----
    if (warp == 0) {
        const float dqi = warp_sum(dot4(zq4, zi4));
        if (lane == 0) s_muxy = -(aq + ai - 2.f * rq * riv * dqi);
    }
    if (warp == 7) {
        const float nn = warp_sum(dot4(zn4, zn4));
        const float dn = warp_sum(dot4(zq4, zn4));
        if (lane == 0) {
            const float rn = rsqrtf(fmaxf(nn, 1e-24f));
            const float mu = -(aq + nn * rn * rn - 2.f * rq * rn * dn);
            const float sg = 1.f / (1.f + expf(-mu));
            g_neg[b] = -logf(1.f - sg + 1e-8f);
        }
    }
    if (t == 0) {
        const float dc = core[nbr] - core[q];
        g_core[b] = dc * dc;
    }
    __syncthreads();  // publish s_mu1/s_mu2/s_te/s_muxy

    // ---- softmaxes: warp0 -> term1, warp1 -> term2 (exact ref math) ----
    if (warp < 2) {
        const float mu = (warp == 0) ? s_mu1[lane] : s_mu2[lane];
        const float te = (warp == 0) ? s_te[lane] : s_te[DEG + lane];
        const float w = expf(mu / TEMP - te);
        const float S = warp_sum(w);
        const float a = w / (S + 1e-8f);
        const float term = warp_sum(a * mu);
        if (lane == 0) s_t12[warp] = term;
    }
    __syncthreads();

    if (t == 0) {
        const float mu_xy = s_muxy;
        const float sg = 1.f / (1.f + expf(-mu_xy));
        g_pos[b] = -logf(sg + 1e-8f);
        const float dd = s_t12[0] + s_t12[1];  // lambda_T - lambda_S
        const float ad = fabsf(dd);
        g_align[b] = (ad < 1.f) ? 0.5f * dd * dd : (ad - 0.5f);
    }

    // ---- completion: last-arriving block reduces (deterministic order) ----
    __threadfence();
    __syncthreads();
    if (t == 0) {
        const int c = atomicAdd(&g_count, 1);
        s_isLast = (c == (int)gridDim.x - 1);
    }
    __syncthreads();
    if (s_isLast) {
        __threadfence();
        const float v = g_pos[t] * (1.f / PP) + g_neg[t] * (1.f / KK)
                      + (0.1f / PP) * (g_core[t] + g_align[t]);
        const float s = warp_sum(v);
        if (lane == 0) s_ws[warp] = s;
        __syncthreads();
        if (t == 0) {
            float tot = 0.f;
#pragma unroll
            for (int w = 0; w < 8; w++) tot += s_ws[w];
            out[0] = tot;
            g_count = 0;  // reset for next graph replay
        }
    }
}

// ---------------------------------------------------------------------------
// Inputs (metadata order):
// 0 z [N*D] f32, 1 edge_times [N*N] f32, 2 current_time [1] f32,
// 3 core_values [N] f32, 4 omega [F] f32, 5 phi [F] f32,
// 6 query_idx [1] i32, 7 neg_idxs [K] i32, 8 neighbor_idxs [P] i32,
// 9 neighbors [N*DEG] i32. Output: [1] f32.
// ---------------------------------------------------------------------------
extern "C" void kernel_launch(void* const* d_in, const int* in_sizes, int n_in,
                              void* d_out, int out_size) {
    const float* z     = (const float*)d_in[0];
    const float* et    = (const float*)d_in[1];
    const float* ct    = (const float*)d_in[2];
    const float* core  = (const float*)d_in[3];
    const float* omega = (const float*)d_in[4];
    const float* phi   = (const float*)d_in[5];
    const int*   qidx  = (const int*)d_in[6];
    const int*   negi  = (const int*)d_in[7];
    const int*   nbri  = (const int*)d_in[8];
    const int*   nbrs  = (const int*)d_in[9];

    fused_kernel<<<PP, 256>>>(z, et, ct, core, omega, phi,
                              qidx, negi, nbri, nbrs, (float*)d_out);
}

// round 4
// speedup vs baseline: 1.2216x; 1.2216x over previous
#include <cuda_runtime.h>

#define NN 8192
#define DD 128
#define PP 256
#define KK 256
#define DEG 32
#define FF 16
#define INV_TEMP (1.0f / 0.07f)
#define FULL 0xffffffffu

// Scratch (__device__ globals; no allocations allowed)
__device__ float g_t1[PP], g_t2[PP], g_posc[PP], g_neg[KK];
__device__ int   g_count = 0;

__device__ __forceinline__ float warp_sum(float v) {
#pragma unroll
    for (int o = 16; o; o >>= 1) v += __shfl_xor_sync(FULL, v, o);
    return v;
}

__device__ __forceinline__ float dot4(float4 a, float4 b) {
    return a.x * b.x + a.y * b.y + a.z * b.z + a.w * b.w;
}

// ---------------------------------------------------------------------------
// Grid = 2*PP = 512 blocks x 256 threads (8 warps).
//   block b in [0,PP):      term1 for neighbor i=b, plus mu_xy/pos/core
//   block b in [PP,2PP):    term2 for neighbor i=b-PP, plus negative i
// Each warp handles 4 rows of the 32-row neighborhood: 9 warp reductions.
// The align loss (needs term1+term2) is computed by the last-arriving block.
// ---------------------------------------------------------------------------
__global__ void __launch_bounds__(256)
fused_kernel(const float* __restrict__ z,
             const float* __restrict__ et,
             const float* __restrict__ ct,
             const float* __restrict__ core,
             const float* __restrict__ omega,
             const float* __restrict__ phi,
             const int* __restrict__ qidx,
             const int* __restrict__ neg_idxs,
             const int* __restrict__ nbr_idxs,
             const int* __restrict__ neighbors,
             float* __restrict__ out) {
    __shared__ float s_mu[DEG], s_te[DEG];
    __shared__ float s_ws[8];
    __shared__ bool  s_isLast;

    const int t = threadIdx.x, lane = t & 31, warp = t >> 5;
    const int b = blockIdx.x;
    const bool isT1 = (b < PP);
    const int  i = isT1 ? b : b - PP;

    // ---- level-0 scalars ----
    const int   q   = qidx[0];
    const int   nbr = nbr_idxs[i];
    const float ct0 = ct[0];
    const int   baseRow = isT1 ? q : nbr;   // whose neighborhood
    const int   refRow  = isT1 ? nbr : q;   // vector dotted against rows

    // core values early (term1 block, thread 0 only)
    float cq = 0.f, ci = 0.f;
    if (isT1 && t == 0) { cq = core[q]; ci = core[nbr]; }

    // ---- level-1 gathers ----
    const float4 ref4 = ((const float4*)(z + (long long)refRow * DD))[lane];
    int myidx = 0;
    if (lane < 4) myidx = neighbors[baseRow * DEG + 4 * warp + lane];

    // warp-0-of-term1 extra: z_q for mu_xy ; warp-7-of-term2 extra: negative
    float4 aux4 = make_float4(0.f, 0.f, 0.f, 0.f);
    int negy = 0;
    if (isT1) {
        if (warp == 0) aux4 = ((const float4*)(z + (long long)q * DD))[lane];
    } else if (warp == 7) {
        negy = neg_idxs[i];
        aux4 = ((const float4*)(z + (long long)negy * DD))[lane];
    }

    // ---- level-2 gathers: 4 rows per warp + 4 edge-time scalars ----
    float4 row[4];
#pragma unroll
    for (int r = 0; r < 4; r++) {
        const int ri = __shfl_sync(FULL, myidx, r);
        row[r] = ((const float4*)(z + (long long)ri * DD))[lane];
    }
    float mydt = 0.f;
    if (lane < 4) mydt = ct0 - et[(long long)baseRow * NN + myidx];

    // ---- reference-vector norm ----
    const float nref = warp_sum(dot4(ref4, ref4));
    const float rref = rsqrtf(fmaxf(nref, 1e-24f));
    const float aref = nref * rref * rref;   // ||ref_hat||^2

    // ---- time encodings: 8 lanes per dt (4 dts per warp) ----
    {
        const int g = lane >> 3, sub = lane & 7;
        const float dtv = __shfl_sync(FULL, mydt, g);
        float p = __sinf(omega[1 + sub] * dtv + phi[1 + sub]);
        if (sub < 7) p += __sinf(omega[9 + sub] * dtv + phi[9 + sub]);
        p += __shfl_xor_sync(FULL, p, 1);
        p += __shfl_xor_sync(FULL, p, 2);
        p += __shfl_xor_sync(FULL, p, 4);
        if (sub == 0) s_te[4 * warp + g] = omega[0] * dtv + phi[0] + p;
    }

    // ---- row dots -> mu values ----
#pragma unroll
    for (int r = 0; r < 4; r++) {
        const float nr = warp_sum(dot4(row[r], row[r]));
        const float dr = warp_sum(dot4(ref4, row[r]));
        if (lane == 0) {
            const float rr = rsqrtf(fmaxf(nr, 1e-24f));
            const float ar = nr * rr * rr;
            s_mu[4 * warp + r] = -(aref + ar - 2.f * rref * rr * dr);
        }
    }

    // ---- per-block extras ----
    float mu_xy = 0.f;
    if (isT1) {
        if (warp == 0) {
            const float nq_ = warp_sum(dot4(aux4, aux4));
            const float dqi = warp_sum(dot4(aux4, ref4));
            const float rq  = rsqrtf(fmaxf(nq_, 1e-24f));
            const float aq  = nq_ * rq * rq;
            mu_xy = -(aq + aref - 2.f * rq * rref * dqi);  // lane0 uses it
        }
    } else if (warp == 7) {
        const float nn = warp_sum(dot4(aux4, aux4));
        const float dn = warp_sum(dot4(aux4, ref4));     // ref4 here is z_q
        if (lane == 0) {
            const float rn = rsqrtf(fmaxf(nn, 1e-24f));
            const float an = nn * rn * rn;
            const float mu = -(aref + an - 2.f * rref * rn * dn);
            const float sg = 1.f / (1.f + __expf(-mu));
            g_neg[i] = -__logf(1.f - sg + 1e-8f) * (1.f / KK);
        }
    }
    __syncthreads();  // publish s_mu / s_te

    // ---- softmax (warp 0), exact reference formula ----
    if (warp == 0) {
        const float mu = s_mu[lane];
        const float w = __expf(mu * INV_TEMP - s_te[lane]);
        const float S = warp_sum(w);
        const float a = w / (S + 1e-8f);
        const float term = warp_sum(a * mu);
        if (lane == 0) {
            if (isT1) {
                g_t1[i] = term;
                const float sg = 1.f / (1.f + __expf(-mu_xy));
                const float dc = ci - cq;
                g_posc[i] = -__logf(sg + 1e-8f) * (1.f / PP)
                          + (0.1f / PP) * dc * dc;
            } else {
                g_t2[i] = term;
            }
        }
    }

    // ---- completion: last-arriving block computes align + total ----
    __threadfence();
    __syncthreads();
    if (t == 0) {
        const int c = atomicAdd(&g_count, 1);
        s_isLast = (c == (int)gridDim.x - 1);
    }
    __syncthreads();
    if (s_isLast) {
        __threadfence();
        const float dd = g_t1[t] + g_t2[t];         // lambda_T - lambda_S
        const float ad = fabsf(dd);
        const float al = (ad < 1.f) ? 0.5f * dd * dd : (ad - 0.5f);
        const float v = g_posc[t] + g_neg[t] + al * (0.1f / PP);
        const float s = warp_sum(v);
        if (lane == 0) s_ws[warp] = s;
        __syncthreads();
        if (t == 0) {
            float tot = 0.f;
#pragma unroll
            for (int w = 0; w < 8; w++) tot += s_ws[w];
            out[0] = tot;
            g_count = 0;  // reset for next graph replay
        }
    }
}

// ---------------------------------------------------------------------------
// Inputs (metadata order):
// 0 z [N*D] f32, 1 edge_times [N*N] f32, 2 current_time [1] f32,
// 3 core_values [N] f32, 4 omega [F] f32, 5 phi [F] f32,
// 6 query_idx [1] i32, 7 neg_idxs [K] i32, 8 neighbor_idxs [P] i32,
// 9 neighbors [N*DEG] i32. Output: [1] f32.
// ---------------------------------------------------------------------------
extern "C" void kernel_launch(void* const* d_in, const int* in_sizes, int n_in,
                              void* d_out, int out_size) {
    const float* z     = (const float*)d_in[0];
    const float* et    = (const float*)d_in[1];
    const float* ct    = (const float*)d_in[2];
    const float* core  = (const float*)d_in[3];
    const float* omega = (const float*)d_in[4];
    const float* phi   = (const float*)d_in[5];
    const int*   qidx  = (const int*)d_in[6];
    const int*   negi  = (const int*)d_in[7];
    const int*   nbri  = (const int*)d_in[8];
    const int*   nbrs  = (const int*)d_in[9];

    fused_kernel<<<2 * PP, 256>>>(z, et, ct, core, omega, phi,
                                  qidx, negi, nbri, nbrs, (float*)d_out);
}